// round 9
// baseline (speedup 1.0000x reference)
#include <cuda_runtime.h>
#include <cuda_bf16.h>

#define U_CNT 50000
#define I_CNT 100000
#define N_CNT 150000
#define D 128
#define NL 3
#define BATCH 4096
#define MAXE 4800000
#define SCAN_ELEMS 2048
#define SCAN_BLOCKS ((N_CNT + SCAN_ELEMS - 1) / SCAN_ELEMS)   // 74

// Scratch (device globals: the allowed scratch mechanism)
__device__ float          g_ego [(size_t)N_CNT * D];             // fp32 ego (for prod term)
__device__ __nv_bfloat16  g_egob[(size_t)N_CNT * D];             // bf16 mirror (gather source)
__device__ float          g_final[(size_t)N_CNT * D * (NL + 1)]; // [N, 512] concat
__device__ float          g_acc[2];                              // bpr sum, reg sum
// CSR-by-row edge structure, rebuilt each launch
__device__ int   g_cnt[N_CNT];
__device__ int   g_off[N_CNT + 1];
__device__ int   g_bsum[SCAN_BLOCKS];
__device__ int2  g_sedge[MAXE];       // (col, val-as-bits), row-sorted

// ---- f32x2 helpers (Blackwell packed fp32) --------------------------------
__device__ __forceinline__ unsigned long long pack2(float s) {
    unsigned long long r;
    asm("mov.b64 %0, {%1, %1};" : "=l"(r) : "f"(s));
    return r;
}
__device__ __forceinline__ void ffma2(unsigned long long& d,
                                      unsigned long long a, unsigned long long b) {
    asm("fma.rn.f32x2 %0, %1, %2, %0;" : "+l"(d) : "l"(a), "l"(b));
}
__device__ __forceinline__ float2 unpack2(unsigned long long v) {
    float2 f;
    asm("mov.b64 {%0, %1}, %2;" : "=f"(f.x), "=f"(f.y) : "l"(v));
    return f;
}

// ---------------------------------------------------------------------------
// init: ego/egob = concat(user_emb, item_emb); final[:, :128] = ego; cnt = 0
// ---------------------------------------------------------------------------
__global__ void init_kernel(const float* __restrict__ ue, const float* __restrict__ ie) {
    size_t i = (size_t)blockIdx.x * blockDim.x + threadIdx.x;  // float4 index
    if (i == 0) { g_acc[0] = 0.f; g_acc[1] = 0.f; }
    if (i >= (size_t)N_CNT * (D / 4)) return;
    size_t row = i >> 5;
    int    c4  = (int)(i & 31);
    if (c4 == 0) g_cnt[row] = 0;
    float4 v;
    if (row < U_CNT) v = ((const float4*)ue)[row * (D / 4) + c4];
    else             v = ((const float4*)ie)[(row - U_CNT) * (D / 4) + c4];
    ((float4*)g_ego)[i] = v;
    __nv_bfloat162 b0 = __float22bfloat162_rn(make_float2(v.x, v.y));
    __nv_bfloat162 b1 = __float22bfloat162_rn(make_float2(v.z, v.w));
    uint2 bb;
    bb.x = *(unsigned int*)&b0;
    bb.y = *(unsigned int*)&b1;
    ((uint2*)g_egob)[i] = bb;
    ((float4*)(g_final + row * (size_t)(D * (NL + 1))))[c4] = v;
}

// ---------------------------------------------------------------------------
// CSR build: histogram -> 3-phase exclusive scan -> scatter
// ---------------------------------------------------------------------------
__global__ void hist_kernel(const int* __restrict__ erow, int nnz) {
    int e = blockIdx.x * blockDim.x + threadIdx.x;
    if (e < nnz) atomicAdd(&g_cnt[erow[e]], 1);
}

__global__ void __launch_bounds__(256) scan1_kernel() {
    __shared__ int s_warp[8];
    int b = blockIdx.x, t = threadIdx.x;
    int lane = t & 31, wid = t >> 5;
    int base = b * SCAN_ELEMS + t * 8;
    int v[8], tot = 0;
#pragma unroll
    for (int j = 0; j < 8; j++) {
        int idx = base + j;
        v[j] = (idx < N_CNT) ? g_cnt[idx] : 0;
        tot += v[j];
    }
    int inc = tot;
#pragma unroll
    for (int off = 1; off < 32; off <<= 1) {
        int y = __shfl_up_sync(0xffffffffu, inc, off);
        if (lane >= off) inc += y;
    }
    if (lane == 31) s_warp[wid] = inc;
    __syncthreads();
    if (t < 8) {
        int w = s_warp[t];
        int winc = w;
#pragma unroll
        for (int off = 1; off < 8; off <<= 1) {
            int y = __shfl_up_sync(0xffu, winc, off);
            if (t >= off) winc += y;
        }
        s_warp[t] = winc - w;
    }
    __syncthreads();
    int run = inc - tot + s_warp[wid];
    if (t == 255) g_bsum[b] = run + tot;
#pragma unroll
    for (int j = 0; j < 8; j++) {
        int idx = base + j;
        if (idx < N_CNT) g_off[idx] = run;
        run += v[j];
    }
}

__global__ void scan2_kernel() {
    __shared__ int s_warp[4];
    int t = threadIdx.x, lane = t & 31, wid = t >> 5;
    int x = (t < SCAN_BLOCKS) ? g_bsum[t] : 0;
    int inc = x;
#pragma unroll
    for (int off = 1; off < 32; off <<= 1) {
        int y = __shfl_up_sync(0xffffffffu, inc, off);
        if (lane >= off) inc += y;
    }
    if (lane == 31) s_warp[wid] = inc;
    __syncthreads();
    if (t < 4) {
        int w = s_warp[t];
        int winc = w;
#pragma unroll
        for (int off = 1; off < 4; off <<= 1) {
            int y = __shfl_up_sync(0xfu, winc, off);
            if (t >= off) winc += y;
        }
        s_warp[t] = winc - w;
    }
    __syncthreads();
    if (t < SCAN_BLOCKS) g_bsum[t] = inc - x + s_warp[wid];
}

__global__ void scan3_kernel(int nnz) {
    int i = blockIdx.x * blockDim.x + threadIdx.x;
    if (i == 0) g_off[N_CNT] = nnz;
    if (i >= N_CNT) return;
    int o = g_off[i] + g_bsum[i >> 11];  // SCAN_ELEMS = 2048
    g_off[i] = o;
    g_cnt[i] = o;
}

__global__ void scatter_kernel(const int* __restrict__ erow, const int* __restrict__ ecol,
                               const float* __restrict__ ev, int nnz) {
    int e = blockIdx.x * blockDim.x + threadIdx.x;
    if (e >= nnz) return;
    int r = erow[e];
    int pos = atomicAdd(&g_cnt[r], 1);
    g_sedge[pos] = make_int2(ecol[e], __float_as_int(ev[e]));
}

// ---------------------------------------------------------------------------
// fused layer: SpMM (bf16 gather, warp-per-row, regs) -> smem -> dual GEMM
// (f32x2) -> lrelu -> norm -> writes.  64 rows/block, 256 threads, each warp
// owns rows w*8..w*8+7 end-to-end (only __syncwarp between phases).
// Phase-2 mapping: lane = (rgrp=lane>>4)*4 rows x (cgrp=lane&15)*8 cols.
// ---------------------------------------------------------------------------
__global__ void __launch_bounds__(256, 2) layer_kernel(
    const float* __restrict__ Wg, const float* __restrict__ Wb,
    const float* __restrict__ bg, const float* __restrict__ bb,
    int lplus1, int write_ego) {
    __shared__ float s_side[64 * D];
    __shared__ float s_prod[64 * D];
    const int tid  = threadIdx.x;
    const int lane = tid & 31;
    const int w    = tid >> 5;
    const int row0 = blockIdx.x * 64;

    // ---- phase 1: SpMM for this warp's 8 rows -----------------------------
    for (int rr = 0; rr < 8; rr++) {
        int lr  = w * 8 + rr;
        int row = row0 + lr;
        float4 acc = make_float4(0.f, 0.f, 0.f, 0.f);
        float4 eg  = acc;
        if (row < N_CNT) {
            int s = __ldg(&g_off[row]);
            int e = __ldg(&g_off[row + 1]);
            for (int base = s; base < e; base += 32) {
                int n = min(32, e - base);
                int2 ed = (lane < n) ? g_sedge[base + lane] : make_int2(0, 0);
                for (int j = 0; j < n; j++) {
                    int   col = __shfl_sync(0xffffffffu, ed.x, j);
                    float v   = __int_as_float(__shfl_sync(0xffffffffu, ed.y, j));
                    uint2 b = __ldg(((const uint2*)(g_egob + (size_t)col * D)) + lane);
                    float2 lo = __bfloat1622float2(*(__nv_bfloat162*)&b.x);
                    float2 hi = __bfloat1622float2(*(__nv_bfloat162*)&b.y);
                    acc.x += v * lo.x; acc.y += v * lo.y;
                    acc.z += v * hi.x; acc.w += v * hi.y;
                }
            }
            eg = ((const float4*)(g_ego + (size_t)row * D))[lane];
        }
        ((float4*)(s_side + lr * D))[lane] = acc;
        ((float4*)(s_prod + lr * D))[lane] =
            make_float4(acc.x * eg.x, acc.y * eg.y, acc.z * eg.z, acc.w * eg.w);
    }
    __syncwarp();

    // ---- phase 2: out = lrelu(side@Wg + prod@Wb + bias), f32x2 ------------
    const int lr0 = w * 8 + (lane >> 4) * 4;   // first of 4 rows
    const int c0  = (lane & 15) * 8;           // first of 8 cols

    unsigned long long acc2[4][4];
#pragma unroll
    for (int r = 0; r < 4; r++)
#pragma unroll
        for (int p = 0; p < 4; p++) acc2[r][p] = 0ull;

#pragma unroll 4
    for (int k = 0; k < D; k++) {
        const ulonglong2* wgp = (const ulonglong2*)(Wg + (size_t)k * D + c0);
        const ulonglong2* wbp = (const ulonglong2*)(Wb + (size_t)k * D + c0);
        ulonglong2 wga = wgp[0], wgb = wgp[1];
        ulonglong2 wba = wbp[0], wbb = wbp[1];
#pragma unroll
        for (int r = 0; r < 4; r++) {
            unsigned long long svp = pack2(s_side[(lr0 + r) * D + k]);
            unsigned long long pvp = pack2(s_prod[(lr0 + r) * D + k]);
            ffma2(acc2[r][0], svp, wga.x);
            ffma2(acc2[r][1], svp, wga.y);
            ffma2(acc2[r][2], svp, wgb.x);
            ffma2(acc2[r][3], svp, wgb.y);
            ffma2(acc2[r][0], pvp, wba.x);
            ffma2(acc2[r][1], pvp, wba.y);
            ffma2(acc2[r][2], pvp, wbb.x);
            ffma2(acc2[r][3], pvp, wbb.y);
        }
    }

    float bias[8];
    {
        float4 a0 = __ldg((const float4*)(bg + c0));
        float4 a1 = __ldg((const float4*)(bg + c0 + 4));
        float4 b0 = __ldg((const float4*)(bb + c0));
        float4 b1 = __ldg((const float4*)(bb + c0 + 4));
        bias[0] = a0.x + b0.x; bias[1] = a0.y + b0.y;
        bias[2] = a0.z + b0.z; bias[3] = a0.w + b0.w;
        bias[4] = a1.x + b1.x; bias[5] = a1.y + b1.y;
        bias[6] = a1.z + b1.z; bias[7] = a1.w + b1.w;
    }

#pragma unroll
    for (int r = 0; r < 4; r++) {
        int gr = row0 + lr0 + r;
        float v[8];
        float ss = 0.f;
#pragma unroll
        for (int p = 0; p < 4; p++) {
            float2 f = unpack2(acc2[r][p]);
            float x0 = f.x + bias[2 * p];
            float x1 = f.y + bias[2 * p + 1];
            x0 = (x0 >= 0.f) ? x0 : 0.2f * x0;
            x1 = (x1 >= 0.f) ? x1 : 0.2f * x1;
            v[2 * p] = x0; v[2 * p + 1] = x1;
            ss += x0 * x0 + x1 * x1;
        }
        // reduce over the 16 lanes covering this row's 128 cols
#pragma unroll
        for (int off = 8; off; off >>= 1) ss += __shfl_xor_sync(0xffffffffu, ss, off);
        float inv = 1.0f / fmaxf(sqrtf(ss), 1e-12f);
        if (gr < N_CNT) {
            float4 o0 = make_float4(v[0], v[1], v[2], v[3]);
            float4 o1 = make_float4(v[4], v[5], v[6], v[7]);
            if (write_ego) {
                float4* eo = (float4*)(g_ego + (size_t)gr * D + c0);
                eo[0] = o0; eo[1] = o1;
                __nv_bfloat162 h0 = __float22bfloat162_rn(make_float2(v[0], v[1]));
                __nv_bfloat162 h1 = __float22bfloat162_rn(make_float2(v[2], v[3]));
                __nv_bfloat162 h2 = __float22bfloat162_rn(make_float2(v[4], v[5]));
                __nv_bfloat162 h3 = __float22bfloat162_rn(make_float2(v[6], v[7]));
                uint4 hb;
                hb.x = *(unsigned int*)&h0; hb.y = *(unsigned int*)&h1;
                hb.z = *(unsigned int*)&h2; hb.w = *(unsigned int*)&h3;
                *((uint4*)(g_egob + (size_t)gr * D + c0)) = hb;
            }
            float* fo = g_final + (size_t)gr * (D * (NL + 1)) + (size_t)lplus1 * D + c0;
            __stcs((float4*)fo,
                   make_float4(v[0] * inv, v[1] * inv, v[2] * inv, v[3] * inv));
            __stcs((float4*)(fo + 4),
                   make_float4(v[4] * inv, v[5] * inv, v[6] * inv, v[7] * inv));
        }
    }
}

// ---------------------------------------------------------------------------
// loss: one warp per batch sample
// ---------------------------------------------------------------------------
__global__ void loss_kernel(const int* __restrict__ user, const int* __restrict__ pos,
                            const int* __restrict__ neg, const float* __restrict__ item_emb) {
    int lane = threadIdx.x & 31;
    int warp = (blockIdx.x * blockDim.x + threadIdx.x) >> 5;
    if (warp >= BATCH) return;
    const int FW = D * (NL + 1);  // 512
    size_t ur = (size_t)user[warp];
    size_t pr = (size_t)U_CNT + pos[warp];
    size_t nr = (size_t)U_CNT + neg[warp];
    const float4* u4 = (const float4*)(g_final + ur * FW);
    const float4* p4 = (const float4*)(g_final + pr * FW);
    const float4* n4 = (const float4*)(g_final + nr * FW);
    float ps = 0.f, ns = 0.f;
#pragma unroll
    for (int t = 0; t < 4; t++) {
        float4 u = u4[lane + 32 * t];
        float4 p = p4[lane + 32 * t];
        float4 n = n4[lane + 32 * t];
        ps += u.x * p.x + u.y * p.y + u.z * p.z + u.w * p.w;
        ns += u.x * n.x + u.y * n.y + u.z * n.z + u.w * n.w;
    }
    float4 a = ((const float4*)(item_emb + (size_t)pos[warp] * D))[lane];
    float4 b = ((const float4*)(item_emb + (size_t)neg[warp] * D))[lane];
    float rs = a.x * a.x + a.y * a.y + a.z * a.z + a.w * a.w
             + b.x * b.x + b.y * b.y + b.z * b.z + b.w * b.w;
#pragma unroll
    for (int off = 16; off; off >>= 1) {
        ps += __shfl_xor_sync(0xffffffffu, ps, off);
        ns += __shfl_xor_sync(0xffffffffu, ns, off);
        rs += __shfl_xor_sync(0xffffffffu, rs, off);
    }
    if (lane == 0) {
        float x  = ns - ps;
        float sp = fmaxf(x, 0.f) + log1pf(expf(-fabsf(x)));
        atomicAdd(&g_acc[0], sp);
        atomicAdd(&g_acc[1], rs);
    }
}

__global__ void finalize_kernel(float* __restrict__ out) {
    out[0] = g_acc[0] / (float)BATCH;
    out[1] = 1e-4f * 0.5f * g_acc[1] / (float)BATCH;
}

// ---------------------------------------------------------------------------
extern "C" void kernel_launch(void* const* d_in, const int* in_sizes, int n_in,
                              void* d_out, int out_size) {
    const int*   user = (const int*)d_in[0];
    const int*   pos  = (const int*)d_in[1];
    const int*   neg  = (const int*)d_in[2];
    const int*   erow = (const int*)d_in[3];
    const int*   ecol = (const int*)d_in[4];
    const float* evalp = (const float*)d_in[5];
    const float* ue   = (const float*)d_in[6];
    const float* ie   = (const float*)d_in[7];
    const float* Wg   = (const float*)d_in[8];
    const float* bg   = (const float*)d_in[9];
    const float* Wb   = (const float*)d_in[10];
    const float* bb   = (const float*)d_in[11];
    float* out = (float*)d_out;
    int nnz = in_sizes[3];
    if (nnz > MAXE) nnz = MAXE;

    {
        int total = N_CNT * (D / 4);
        init_kernel<<<(total + 255) / 256, 256>>>(ue, ie);
    }
    // Build row-sorted CSR once, reused by all 3 layers
    hist_kernel<<<(nnz + 255) / 256, 256>>>(erow, nnz);
    scan1_kernel<<<SCAN_BLOCKS, 256>>>();
    scan2_kernel<<<1, 128>>>();
    scan3_kernel<<<(N_CNT + 255) / 256, 256>>>(nnz);
    scatter_kernel<<<(nnz + 255) / 256, 256>>>(erow, ecol, evalp, nnz);

    for (int l = 0; l < NL; l++) {
        layer_kernel<<<(N_CNT + 63) / 64, 256>>>(
            Wg + (size_t)l * D * D, Wb + (size_t)l * D * D,
            bg + (size_t)l * D,     bb + (size_t)l * D,
            l + 1, (l < NL - 1) ? 1 : 0);
    }
    loss_kernel<<<(BATCH * 32 + 255) / 256, 256>>>(user, pos, neg, ie);
    finalize_kernel<<<1, 1>>>(out);
}

// round 13
// speedup vs baseline: 1.0604x; 1.0604x over previous
#include <cuda_runtime.h>
#include <cuda_bf16.h>

#define U_CNT 50000
#define I_CNT 100000
#define N_CNT 150000
#define D 128
#define NL 3
#define BATCH 4096
#define MAXE 4800000
#define SCAN_ELEMS 2048
#define SCAN_BLOCKS ((N_CNT + SCAN_ELEMS - 1) / SCAN_ELEMS)   // 74

// Scratch (device globals: the allowed scratch mechanism)
__device__ float g_ego  [(size_t)N_CNT * D];            // current (unnormalized) ego
__device__ float g_side [(size_t)N_CNT * D];            // SpMM output
__device__ float g_final[(size_t)N_CNT * D * (NL + 1)]; // [N, 512] concat
__device__ float g_acc[2];                              // bpr sum, reg sum
// CSR-by-row edge structure, rebuilt each launch
__device__ int   g_cnt[N_CNT];
__device__ int   g_off[N_CNT + 1];
__device__ int   g_bsum[SCAN_BLOCKS];
__device__ int2  g_sedge[MAXE];       // (col, val-as-bits), row-sorted

// ---- f32x2 helpers (Blackwell packed fp32 — only reachable via PTX) -------
__device__ __forceinline__ unsigned long long pack2(float s) {
    unsigned long long r;
    asm("mov.b64 %0, {%1, %1};" : "=l"(r) : "f"(s));
    return r;
}
__device__ __forceinline__ void ffma2(unsigned long long& d,
                                      unsigned long long a, unsigned long long b) {
    asm("fma.rn.f32x2 %0, %1, %2, %0;" : "+l"(d) : "l"(a), "l"(b));
}
__device__ __forceinline__ float2 unpack2(unsigned long long v) {
    float2 f;
    asm("mov.b64 {%0, %1}, %2;" : "=f"(f.x), "=f"(f.y) : "l"(v));
    return f;
}

// ---------------------------------------------------------------------------
// init: ego = concat(user_emb, item_emb); final[:, :128] = ego; cnt = 0
// ---------------------------------------------------------------------------
__global__ void init_kernel(const float* __restrict__ ue, const float* __restrict__ ie) {
    size_t i = (size_t)blockIdx.x * blockDim.x + threadIdx.x;  // float4 index
    if (i == 0) { g_acc[0] = 0.f; g_acc[1] = 0.f; }
    if (i >= (size_t)N_CNT * (D / 4)) return;
    size_t row = i >> 5;
    int    c4  = (int)(i & 31);
    if (c4 == 0) g_cnt[row] = 0;
    float4 v;
    if (row < U_CNT) v = ((const float4*)ue)[row * (D / 4) + c4];
    else             v = ((const float4*)ie)[(row - U_CNT) * (D / 4) + c4];
    ((float4*)g_ego)[i] = v;
    ((float4*)(g_final + row * (size_t)(D * (NL + 1))))[c4] = v;
}

// ---------------------------------------------------------------------------
// CSR build: histogram -> 3-phase exclusive scan -> scatter
// ---------------------------------------------------------------------------
__global__ void hist_kernel(const int* __restrict__ erow, int nnz) {
    int e = blockIdx.x * blockDim.x + threadIdx.x;
    if (e < nnz) atomicAdd(&g_cnt[erow[e]], 1);
}

__global__ void __launch_bounds__(256) scan1_kernel() {
    __shared__ int s_warp[8];
    int b = blockIdx.x, t = threadIdx.x;
    int lane = t & 31, wid = t >> 5;
    int base = b * SCAN_ELEMS + t * 8;
    int v[8], tot = 0;
#pragma unroll
    for (int j = 0; j < 8; j++) {
        int idx = base + j;
        v[j] = (idx < N_CNT) ? g_cnt[idx] : 0;
        tot += v[j];
    }
    int inc = tot;
#pragma unroll
    for (int off = 1; off < 32; off <<= 1) {
        int y = __shfl_up_sync(0xffffffffu, inc, off);
        if (lane >= off) inc += y;
    }
    if (lane == 31) s_warp[wid] = inc;
    __syncthreads();
    if (t < 8) {
        int w = s_warp[t];
        int winc = w;
#pragma unroll
        for (int off = 1; off < 8; off <<= 1) {
            int y = __shfl_up_sync(0xffu, winc, off);
            if (t >= off) winc += y;
        }
        s_warp[t] = winc - w;
    }
    __syncthreads();
    int run = inc - tot + s_warp[wid];
    if (t == 255) g_bsum[b] = run + tot;
#pragma unroll
    for (int j = 0; j < 8; j++) {
        int idx = base + j;
        if (idx < N_CNT) g_off[idx] = run;
        run += v[j];
    }
}

__global__ void scan2_kernel() {
    __shared__ int s_warp[4];
    int t = threadIdx.x, lane = t & 31, wid = t >> 5;
    int x = (t < SCAN_BLOCKS) ? g_bsum[t] : 0;
    int inc = x;
#pragma unroll
    for (int off = 1; off < 32; off <<= 1) {
        int y = __shfl_up_sync(0xffffffffu, inc, off);
        if (lane >= off) inc += y;
    }
    if (lane == 31) s_warp[wid] = inc;
    __syncthreads();
    if (t < 4) {
        int w = s_warp[t];
        int winc = w;
#pragma unroll
        for (int off = 1; off < 4; off <<= 1) {
            int y = __shfl_up_sync(0xfu, winc, off);
            if (t >= off) winc += y;
        }
        s_warp[t] = winc - w;
    }
    __syncthreads();
    if (t < SCAN_BLOCKS) g_bsum[t] = inc - x + s_warp[wid];
}

__global__ void scan3_kernel(int nnz) {
    int i = blockIdx.x * blockDim.x + threadIdx.x;
    if (i == 0) g_off[N_CNT] = nnz;
    if (i >= N_CNT) return;
    int o = g_off[i] + g_bsum[i >> 11];  // SCAN_ELEMS = 2048
    g_off[i] = o;
    g_cnt[i] = o;
}

__global__ void scatter_kernel(const int* __restrict__ erow, const int* __restrict__ ecol,
                               const float* __restrict__ ev, int nnz) {
    int e = blockIdx.x * blockDim.x + threadIdx.x;
    if (e >= nnz) return;
    int r = erow[e];
    int pos = atomicAdd(&g_cnt[r], 1);
    g_sedge[pos] = make_int2(ecol[e], __float_as_int(ev[e]));
}

// ---------------------------------------------------------------------------
// spmm (CSR): one warp per row, fp32 gather, register accumulation, no atomics
// ---------------------------------------------------------------------------
__global__ void __launch_bounds__(256) spmm_csr_kernel() {
    int lane = threadIdx.x & 31;
    int row  = (blockIdx.x * blockDim.x + threadIdx.x) >> 5;
    if (row >= N_CNT) return;
    int s = __ldg(&g_off[row]);
    int e = __ldg(&g_off[row + 1]);
    float4 acc = make_float4(0.f, 0.f, 0.f, 0.f);
    for (int base = s; base < e; base += 32) {
        int n = min(32, e - base);
        int2 ed = (lane < n) ? g_sedge[base + lane] : make_int2(0, 0);
        for (int j = 0; j < n; j++) {
            int   col = __shfl_sync(0xffffffffu, ed.x, j);
            float v   = __int_as_float(__shfl_sync(0xffffffffu, ed.y, j));
            float4 x = __ldg(((const float4*)(g_ego + (size_t)col * D)) + lane);
            acc.x += v * x.x; acc.y += v * x.y;
            acc.z += v * x.z; acc.w += v * x.w;
        }
    }
    __stcs(((float4*)(g_side + (size_t)row * D)) + lane, acc);
}

// ---------------------------------------------------------------------------
// transform: ego' = lrelu(side@Wg + (ego*side)@Wb + bg + bb)
//            final[:, (l+1)*128:] = ego'/||ego'||
// 64 rows/block, 256 threads. Thread (rg=tid>>4, cg=tid&15) owns
// rows rg*4..+3, cols cg*8..+7 (4 f32x2 col-pairs). FFMA2 GEMM core.
// ---------------------------------------------------------------------------
__global__ void __launch_bounds__(256) transform_kernel(
    const float* __restrict__ Wg, const float* __restrict__ Wb,
    const float* __restrict__ bg, const float* __restrict__ bb,
    int lplus1, int write_ego) {
    __shared__ float s_side[64 * D];
    __shared__ float s_prod[64 * D];
    const int row0 = blockIdx.x * 64;
    const int tid  = threadIdx.x;

    // stage side + ego*side tiles
    for (int i = tid; i < 64 * (D / 4); i += 256) {
        int r  = i >> 5;
        int c4 = i & 31;
        int gr = row0 + r;
        float4 sd = make_float4(0.f, 0.f, 0.f, 0.f);
        float4 eg = sd;
        if (gr < N_CNT) {
            sd = __ldcs(((const float4*)(g_side + (size_t)gr * D)) + c4);
            eg = ((const float4*)(g_ego  + (size_t)gr * D))[c4];
        }
        ((float4*)s_side)[i] = sd;
        ((float4*)s_prod)[i] = make_float4(sd.x * eg.x, sd.y * eg.y, sd.z * eg.z, sd.w * eg.w);
    }
    __syncthreads();

    const int cg  = tid & 15;       // 16 col groups of 8
    const int rg  = tid >> 4;       // 16 row groups of 4
    const int lr0 = rg * 4;
    const int c0  = cg * 8;

    unsigned long long acc2[4][4];  // [row][col-pair]
#pragma unroll
    for (int r = 0; r < 4; r++)
#pragma unroll
        for (int p = 0; p < 4; p++) acc2[r][p] = 0ull;

#pragma unroll 2
    for (int k4 = 0; k4 < 32; k4++) {
        float4 sv[4], pv[4];
#pragma unroll
        for (int r = 0; r < 4; r++) {
            sv[r] = ((const float4*)(s_side + (lr0 + r) * D))[k4];
            pv[r] = ((const float4*)(s_prod + (lr0 + r) * D))[k4];
        }
#pragma unroll
        for (int kk = 0; kk < 4; kk++) {
            const int k = k4 * 4 + kk;
            // adjacent cols are contiguous: load weights directly as f32x2 pairs
            ulonglong2 wg0 = __ldg((const ulonglong2*)(Wg + (size_t)k * D + c0));
            ulonglong2 wg1 = __ldg((const ulonglong2*)(Wg + (size_t)k * D + c0 + 4));
            ulonglong2 wb0 = __ldg((const ulonglong2*)(Wb + (size_t)k * D + c0));
            ulonglong2 wb1 = __ldg((const ulonglong2*)(Wb + (size_t)k * D + c0 + 4));
#pragma unroll
            for (int r = 0; r < 4; r++) {
                float s = (kk == 0) ? sv[r].x : (kk == 1) ? sv[r].y : (kk == 2) ? sv[r].z : sv[r].w;
                float p = (kk == 0) ? pv[r].x : (kk == 1) ? pv[r].y : (kk == 2) ? pv[r].z : pv[r].w;
                unsigned long long sp = pack2(s);
                unsigned long long pp = pack2(p);
                ffma2(acc2[r][0], sp, wg0.x);
                ffma2(acc2[r][1], sp, wg0.y);
                ffma2(acc2[r][2], sp, wg1.x);
                ffma2(acc2[r][3], sp, wg1.y);
                ffma2(acc2[r][0], pp, wb0.x);
                ffma2(acc2[r][1], pp, wb0.y);
                ffma2(acc2[r][2], pp, wb1.x);
                ffma2(acc2[r][3], pp, wb1.y);
            }
        }
    }

    float bias[8];
    {
        float4 a0 = __ldg((const float4*)(bg + c0));
        float4 a1 = __ldg((const float4*)(bg + c0 + 4));
        float4 b0 = __ldg((const float4*)(bb + c0));
        float4 b1 = __ldg((const float4*)(bb + c0 + 4));
        bias[0] = a0.x + b0.x; bias[1] = a0.y + b0.y;
        bias[2] = a0.z + b0.z; bias[3] = a0.w + b0.w;
        bias[4] = a1.x + b1.x; bias[5] = a1.y + b1.y;
        bias[6] = a1.z + b1.z; bias[7] = a1.w + b1.w;
    }

#pragma unroll
    for (int r = 0; r < 4; r++) {
        int gr = row0 + lr0 + r;
        float v[8];
        float ss = 0.f;
#pragma unroll
        for (int p = 0; p < 4; p++) {
            float2 f = unpack2(acc2[r][p]);
            float x0 = f.x + bias[2 * p];
            float x1 = f.y + bias[2 * p + 1];
            x0 = (x0 >= 0.f) ? x0 : 0.2f * x0;
            x1 = (x1 >= 0.f) ? x1 : 0.2f * x1;
            v[2 * p] = x0; v[2 * p + 1] = x1;
            ss += x0 * x0 + x1 * x1;
        }
        // the 16 lanes of this half-warp hold this row's 128 cols
#pragma unroll
        for (int off = 8; off; off >>= 1) ss += __shfl_xor_sync(0xffffffffu, ss, off);
        float inv = 1.0f / fmaxf(sqrtf(ss), 1e-12f);
        if (gr < N_CNT) {
            if (write_ego) {
                float4* eo = (float4*)(g_ego + (size_t)gr * D + c0);
                eo[0] = make_float4(v[0], v[1], v[2], v[3]);
                eo[1] = make_float4(v[4], v[5], v[6], v[7]);
            }
            float* fo = g_final + (size_t)gr * (D * (NL + 1)) + (size_t)lplus1 * D + c0;
            __stcs((float4*)fo,
                   make_float4(v[0] * inv, v[1] * inv, v[2] * inv, v[3] * inv));
            __stcs((float4*)(fo + 4),
                   make_float4(v[4] * inv, v[5] * inv, v[6] * inv, v[7] * inv));
        }
    }
}

// ---------------------------------------------------------------------------
// loss: one warp per batch sample
// ---------------------------------------------------------------------------
__global__ void loss_kernel(const int* __restrict__ user, const int* __restrict__ pos,
                            const int* __restrict__ neg, const float* __restrict__ item_emb) {
    int lane = threadIdx.x & 31;
    int warp = (blockIdx.x * blockDim.x + threadIdx.x) >> 5;
    if (warp >= BATCH) return;
    const int FW = D * (NL + 1);  // 512
    size_t ur = (size_t)user[warp];
    size_t pr = (size_t)U_CNT + pos[warp];
    size_t nr = (size_t)U_CNT + neg[warp];
    const float4* u4 = (const float4*)(g_final + ur * FW);
    const float4* p4 = (const float4*)(g_final + pr * FW);
    const float4* n4 = (const float4*)(g_final + nr * FW);
    float ps = 0.f, ns = 0.f;
#pragma unroll
    for (int t = 0; t < 4; t++) {
        float4 u = u4[lane + 32 * t];
        float4 p = p4[lane + 32 * t];
        float4 n = n4[lane + 32 * t];
        ps += u.x * p.x + u.y * p.y + u.z * p.z + u.w * p.w;
        ns += u.x * n.x + u.y * n.y + u.z * n.z + u.w * n.w;
    }
    float4 a = ((const float4*)(item_emb + (size_t)pos[warp] * D))[lane];
    float4 b = ((const float4*)(item_emb + (size_t)neg[warp] * D))[lane];
    float rs = a.x * a.x + a.y * a.y + a.z * a.z + a.w * a.w
             + b.x * b.x + b.y * b.y + b.z * b.z + b.w * b.w;
#pragma unroll
    for (int off = 16; off; off >>= 1) {
        ps += __shfl_xor_sync(0xffffffffu, ps, off);
        ns += __shfl_xor_sync(0xffffffffu, ns, off);
        rs += __shfl_xor_sync(0xffffffffu, rs, off);
    }
    if (lane == 0) {
        float x  = ns - ps;
        float sp = fmaxf(x, 0.f) + log1pf(expf(-fabsf(x)));
        atomicAdd(&g_acc[0], sp);
        atomicAdd(&g_acc[1], rs);
    }
}

__global__ void finalize_kernel(float* __restrict__ out) {
    out[0] = g_acc[0] / (float)BATCH;
    out[1] = 1e-4f * 0.5f * g_acc[1] / (float)BATCH;
}

// ---------------------------------------------------------------------------
extern "C" void kernel_launch(void* const* d_in, const int* in_sizes, int n_in,
                              void* d_out, int out_size) {
    const int*   user = (const int*)d_in[0];
    const int*   pos  = (const int*)d_in[1];
    const int*   neg  = (const int*)d_in[2];
    const int*   erow = (const int*)d_in[3];
    const int*   ecol = (const int*)d_in[4];
    const float* evalp = (const float*)d_in[5];
    const float* ue   = (const float*)d_in[6];
    const float* ie   = (const float*)d_in[7];
    const float* Wg   = (const float*)d_in[8];
    const float* bg   = (const float*)d_in[9];
    const float* Wb   = (const float*)d_in[10];
    const float* bb   = (const float*)d_in[11];
    float* out = (float*)d_out;
    int nnz = in_sizes[3];
    if (nnz > MAXE) nnz = MAXE;

    {
        int total = N_CNT * (D / 4);
        init_kernel<<<(total + 255) / 256, 256>>>(ue, ie);
    }
    // Build row-sorted CSR once, reused by all 3 layers
    hist_kernel<<<(nnz + 255) / 256, 256>>>(erow, nnz);
    scan1_kernel<<<SCAN_BLOCKS, 256>>>();
    scan2_kernel<<<1, 128>>>();
    scan3_kernel<<<(N_CNT + 255) / 256, 256>>>(nnz);
    scatter_kernel<<<(nnz + 255) / 256, 256>>>(erow, ecol, evalp, nnz);

    for (int l = 0; l < NL; l++) {
        spmm_csr_kernel<<<(N_CNT * 32 + 255) / 256, 256>>>();
        transform_kernel<<<(N_CNT + 63) / 64, 256>>>(
            Wg + (size_t)l * D * D, Wb + (size_t)l * D * D,
            bg + (size_t)l * D,     bb + (size_t)l * D,
            l + 1, (l < NL - 1) ? 1 : 0);
    }
    loss_kernel<<<(BATCH * 32 + 255) / 256, 256>>>(user, pos, neg, ie);
    finalize_kernel<<<1, 1>>>(out);
}

// round 15
// speedup vs baseline: 1.5736x; 1.4840x over previous
#include <cuda_runtime.h>
#include <cuda_bf16.h>
#include <cstdint>

#define U_CNT 50000
#define I_CNT 100000
#define N_CNT 150000
#define D 128
#define NL 3
#define BATCH 4096
#define MAXE 4800000
#define SCAN_ELEMS 2048
#define SCAN_BLOCKS ((N_CNT + SCAN_ELEMS - 1) / SCAN_ELEMS)   // 74

// transform tiling
#define A_STRIDE 260            // 64 x 260 staged A ([side|prod]), pad: 260%32=4
#define B_STRIDE 136            // 64 x 136 staged B chunk,        pad: 136%32=8
#define O_STRIDE 132            // 64 x 132 epilogue tile
#define SMF_B    (64 * A_STRIDE)                       // float offset of B region
#define SMEM_FLOATS (64 * A_STRIDE + 64 * B_STRIDE)    // 25344 floats
#define SMEM_BYTES  (SMEM_FLOATS * 4)                  // 101376 B

// Scratch (device globals: the allowed scratch mechanism)
__device__ float g_ego  [(size_t)N_CNT * D];            // current (unnormalized) ego
__device__ float g_side [(size_t)N_CNT * D];            // SpMM output
__device__ float g_final[(size_t)N_CNT * D * (NL + 1)]; // [N, 512] concat
__device__ float g_acc[2];                              // bpr sum, reg sum
// CSR-by-row edge structure, rebuilt each launch
__device__ int   g_cnt[N_CNT];
__device__ int   g_off[N_CNT + 1];
__device__ int   g_bsum[SCAN_BLOCKS];
__device__ int2  g_sedge[MAXE];       // (col, val-as-bits), row-sorted

// ---- tf32 helpers ---------------------------------------------------------
__device__ __forceinline__ float tf32r(float x) {
    uint32_t r;
    asm("cvt.rna.tf32.f32 %0, %1;" : "=r"(r) : "f"(x));
    return __uint_as_float(r);
}
__device__ __forceinline__ void mma_tf32(float* c, uint32_t a0, uint32_t a1,
                                         uint32_t a2, uint32_t a3,
                                         uint32_t b0, uint32_t b1) {
    asm("mma.sync.aligned.m16n8k8.row.col.f32.tf32.tf32.f32 "
        "{%0,%1,%2,%3},{%4,%5,%6,%7},{%8,%9},{%0,%1,%2,%3};"
        : "+f"(c[0]), "+f"(c[1]), "+f"(c[2]), "+f"(c[3])
        : "r"(a0), "r"(a1), "r"(a2), "r"(a3), "r"(b0), "r"(b1));
}

// ---------------------------------------------------------------------------
// init: ego = concat(user_emb, item_emb); final[:, :128] = ego; cnt = 0
// ---------------------------------------------------------------------------
__global__ void init_kernel(const float* __restrict__ ue, const float* __restrict__ ie) {
    size_t i = (size_t)blockIdx.x * blockDim.x + threadIdx.x;  // float4 index
    if (i == 0) { g_acc[0] = 0.f; g_acc[1] = 0.f; }
    if (i >= (size_t)N_CNT * (D / 4)) return;
    size_t row = i >> 5;
    int    c4  = (int)(i & 31);
    if (c4 == 0) g_cnt[row] = 0;
    float4 v;
    if (row < U_CNT) v = ((const float4*)ue)[row * (D / 4) + c4];
    else             v = ((const float4*)ie)[(row - U_CNT) * (D / 4) + c4];
    ((float4*)g_ego)[i] = v;
    ((float4*)(g_final + row * (size_t)(D * (NL + 1))))[c4] = v;
}

// ---------------------------------------------------------------------------
// CSR build: histogram -> 3-phase exclusive scan -> scatter
// ---------------------------------------------------------------------------
__global__ void hist_kernel(const int* __restrict__ erow, int nnz) {
    int e = blockIdx.x * blockDim.x + threadIdx.x;
    if (e < nnz) atomicAdd(&g_cnt[erow[e]], 1);
}

__global__ void __launch_bounds__(256) scan1_kernel() {
    __shared__ int s_warp[8];
    int b = blockIdx.x, t = threadIdx.x;
    int lane = t & 31, wid = t >> 5;
    int base = b * SCAN_ELEMS + t * 8;
    int v[8], tot = 0;
#pragma unroll
    for (int j = 0; j < 8; j++) {
        int idx = base + j;
        v[j] = (idx < N_CNT) ? g_cnt[idx] : 0;
        tot += v[j];
    }
    int inc = tot;
#pragma unroll
    for (int off = 1; off < 32; off <<= 1) {
        int y = __shfl_up_sync(0xffffffffu, inc, off);
        if (lane >= off) inc += y;
    }
    if (lane == 31) s_warp[wid] = inc;
    __syncthreads();
    if (t < 8) {
        int w = s_warp[t];
        int winc = w;
#pragma unroll
        for (int off = 1; off < 8; off <<= 1) {
            int y = __shfl_up_sync(0xffu, winc, off);
            if (t >= off) winc += y;
        }
        s_warp[t] = winc - w;
    }
    __syncthreads();
    int run = inc - tot + s_warp[wid];
    if (t == 255) g_bsum[b] = run + tot;
#pragma unroll
    for (int j = 0; j < 8; j++) {
        int idx = base + j;
        if (idx < N_CNT) g_off[idx] = run;
        run += v[j];
    }
}

__global__ void scan2_kernel() {
    __shared__ int s_warp[4];
    int t = threadIdx.x, lane = t & 31, wid = t >> 5;
    int x = (t < SCAN_BLOCKS) ? g_bsum[t] : 0;
    int inc = x;
#pragma unroll
    for (int off = 1; off < 32; off <<= 1) {
        int y = __shfl_up_sync(0xffffffffu, inc, off);
        if (lane >= off) inc += y;
    }
    if (lane == 31) s_warp[wid] = inc;
    __syncthreads();
    if (t < 4) {
        int w = s_warp[t];
        int winc = w;
#pragma unroll
        for (int off = 1; off < 4; off <<= 1) {
            int y = __shfl_up_sync(0xfu, winc, off);
            if (t >= off) winc += y;
        }
        s_warp[t] = winc - w;
    }
    __syncthreads();
    if (t < SCAN_BLOCKS) g_bsum[t] = inc - x + s_warp[wid];
}

__global__ void scan3_kernel(int nnz) {
    int i = blockIdx.x * blockDim.x + threadIdx.x;
    if (i == 0) g_off[N_CNT] = nnz;
    if (i >= N_CNT) return;
    int o = g_off[i] + g_bsum[i >> 11];  // SCAN_ELEMS = 2048
    g_off[i] = o;
    g_cnt[i] = o;
}

__global__ void scatter_kernel(const int* __restrict__ erow, const int* __restrict__ ecol,
                               const float* __restrict__ ev, int nnz) {
    int e = blockIdx.x * blockDim.x + threadIdx.x;
    if (e >= nnz) return;
    int r = erow[e];
    int pos = atomicAdd(&g_cnt[r], 1);
    g_sedge[pos] = make_int2(ecol[e], __float_as_int(ev[e]));
}

// ---------------------------------------------------------------------------
// spmm (CSR): one warp per row, fp32 gather, register accumulation, no atomics
// ---------------------------------------------------------------------------
__global__ void __launch_bounds__(256) spmm_csr_kernel() {
    int lane = threadIdx.x & 31;
    int row  = (blockIdx.x * blockDim.x + threadIdx.x) >> 5;
    if (row >= N_CNT) return;
    int s = __ldg(&g_off[row]);
    int e = __ldg(&g_off[row + 1]);
    float4 acc = make_float4(0.f, 0.f, 0.f, 0.f);
    for (int base = s; base < e; base += 32) {
        int n = min(32, e - base);
        int2 ed = (lane < n) ? g_sedge[base + lane] : make_int2(0, 0);
        for (int j = 0; j < n; j++) {
            int   col = __shfl_sync(0xffffffffu, ed.x, j);
            float v   = __int_as_float(__shfl_sync(0xffffffffu, ed.y, j));
            float4 x = __ldg(((const float4*)(g_ego + (size_t)col * D)) + lane);
            acc.x += v * x.x; acc.y += v * x.y;
            acc.z += v * x.z; acc.w += v * x.w;
        }
    }
    __stcs(((float4*)(g_side + (size_t)row * D)) + lane, acc);
}

// ---------------------------------------------------------------------------
// transform (tf32 tensor cores):
//   out = lrelu([side | side*ego] @ [Wg ; Wb] + bg + bb)
//   ego = out (if not last layer); final[:, (l+1)*128:] = out / ||out||
// Block: 64 rows x 128 cols, K=256 in 4 chunks of 64. 8 warps:
// warp w -> row strip (w>>1)*16, col half (w&1)*64. mma m16n8k8 tf32.
// ---------------------------------------------------------------------------
__global__ void __launch_bounds__(256) transform_mma_kernel(
    const float* __restrict__ Wg, const float* __restrict__ Wb,
    const float* __restrict__ bg, const float* __restrict__ bb,
    int lplus1, int write_ego) {
    extern __shared__ float sm[];
    float* sA = sm;            // [64][A_STRIDE]  (cols 0..127 side, 128..255 prod)
    float* sB = sm + SMF_B;    // [64][B_STRIDE]  per-chunk W tile
    float* sO = sm + SMF_B;    // [64][O_STRIDE]  epilogue reuse of B region

    const int tid  = threadIdx.x;
    const int row0 = blockIdx.x * 64;
    const int lane = tid & 31;
    const int w    = tid >> 5;
    const int gid  = lane >> 2;    // 0..7
    const int tig  = lane & 3;     // 0..3
    const int rs   = w >> 1;       // row strip 0..3
    const int ch   = w & 1;        // col half 0..1

    // ---- stage A: [side | side*ego] as tf32 -------------------------------
    for (int idx = tid; idx < 64 * 32; idx += 256) {
        int r  = idx >> 5;
        int c4 = idx & 31;
        int gr = row0 + r;
        float4 sd = make_float4(0.f, 0.f, 0.f, 0.f);
        float4 eg = sd;
        if (gr < N_CNT) {
            sd = __ldcs(((const float4*)(g_side + (size_t)gr * D)) + c4);
            eg = ((const float4*)(g_ego + (size_t)gr * D))[c4];
        }
        float* pa = sA + r * A_STRIDE + c4 * 4;
        pa[0] = tf32r(sd.x); pa[1] = tf32r(sd.y);
        pa[2] = tf32r(sd.z); pa[3] = tf32r(sd.w);
        float* pp = pa + 128;
        pp[0] = tf32r(sd.x * eg.x); pp[1] = tf32r(sd.y * eg.y);
        pp[2] = tf32r(sd.z * eg.z); pp[3] = tf32r(sd.w * eg.w);
    }

    float c[8][4];
#pragma unroll
    for (int nt = 0; nt < 8; nt++)
#pragma unroll
        for (int i = 0; i < 4; i++) c[nt][i] = 0.f;

    // ---- main loop over 4 K-chunks of 64 ----------------------------------
    for (int kc = 0; kc < 4; kc++) {
        __syncthreads();  // also covers A staging on first iter; sB reuse after
        const float* Wsrc = (kc < 2) ? Wg : Wb;
        const int kr0 = (kc & 1) * 64;
        for (int idx = tid; idx < 64 * 32; idx += 256) {
            int k  = idx >> 5;
            int c4 = idx & 31;
            float4 wv = __ldg((const float4*)(Wsrc + (size_t)(kr0 + k) * D + c4 * 4));
            float* pb = sB + k * B_STRIDE + c4 * 4;
            pb[0] = tf32r(wv.x); pb[1] = tf32r(wv.y);
            pb[2] = tf32r(wv.z); pb[3] = tf32r(wv.w);
        }
        __syncthreads();

        const float* Ab = sA + (rs * 16) * A_STRIDE + kc * 64;
#pragma unroll
        for (int ks = 0; ks < 8; ks++) {
            const int kl = ks * 8;
            uint32_t a0 = __float_as_uint(Ab[gid * A_STRIDE + kl + tig]);
            uint32_t a1 = __float_as_uint(Ab[(gid + 8) * A_STRIDE + kl + tig]);
            uint32_t a2 = __float_as_uint(Ab[gid * A_STRIDE + kl + tig + 4]);
            uint32_t a3 = __float_as_uint(Ab[(gid + 8) * A_STRIDE + kl + tig + 4]);
            const float* Bb = sB + (kl + tig) * B_STRIDE + ch * 64 + gid;
#pragma unroll
            for (int nt = 0; nt < 8; nt++) {
                uint32_t b0 = __float_as_uint(Bb[nt * 8]);
                uint32_t b1 = __float_as_uint(Bb[4 * B_STRIDE + nt * 8]);
                mma_tf32(c[nt], a0, a1, a2, a3, b0, b1);
            }
        }
    }
    __syncthreads();  // done reading sB; safe to overwrite as sO

    // ---- bias + lrelu, frags -> sO ----------------------------------------
    const int ra = rs * 16 + gid;
    const int rb = ra + 8;
#pragma unroll
    for (int nt = 0; nt < 8; nt++) {
        int col = ch * 64 + nt * 8 + 2 * tig;
        float b0v = __ldg(bg + col) + __ldg(bb + col);
        float b1v = __ldg(bg + col + 1) + __ldg(bb + col + 1);
        float x0 = c[nt][0] + b0v; x0 = (x0 >= 0.f) ? x0 : 0.2f * x0;
        float x1 = c[nt][1] + b1v; x1 = (x1 >= 0.f) ? x1 : 0.2f * x1;
        float x2 = c[nt][2] + b0v; x2 = (x2 >= 0.f) ? x2 : 0.2f * x2;
        float x3 = c[nt][3] + b1v; x3 = (x3 >= 0.f) ? x3 : 0.2f * x3;
        *(float2*)(sO + ra * O_STRIDE + col) = make_float2(x0, x1);
        *(float2*)(sO + rb * O_STRIDE + col) = make_float2(x2, x3);
    }
    __syncthreads();

    // ---- row norm + global writes (4 threads per row, 32 cols each) -------
    {
        int r     = tid >> 2;
        int cpart = (tid & 3) * 32;
        int gr    = row0 + r;
        float4 vv[8];
        float ss = 0.f;
#pragma unroll
        for (int i = 0; i < 8; i++) {
            vv[i] = *(const float4*)(sO + r * O_STRIDE + cpart + i * 4);
            ss += vv[i].x * vv[i].x + vv[i].y * vv[i].y
                + vv[i].z * vv[i].z + vv[i].w * vv[i].w;
        }
        ss += __shfl_xor_sync(0xffffffffu, ss, 1);
        ss += __shfl_xor_sync(0xffffffffu, ss, 2);
        float inv = 1.0f / fmaxf(sqrtf(ss), 1e-12f);
        if (gr < N_CNT) {
            float4* eo = (float4*)(g_ego + (size_t)gr * D + cpart);
            float*  fo = g_final + (size_t)gr * (D * (NL + 1)) + (size_t)lplus1 * D + cpart;
#pragma unroll
            for (int i = 0; i < 8; i++) {
                if (write_ego) eo[i] = vv[i];
                __stcs((float4*)fo + i,
                       make_float4(vv[i].x * inv, vv[i].y * inv,
                                   vv[i].z * inv, vv[i].w * inv));
            }
        }
    }
}

// ---------------------------------------------------------------------------
// loss: one warp per batch sample
// ---------------------------------------------------------------------------
__global__ void loss_kernel(const int* __restrict__ user, const int* __restrict__ pos,
                            const int* __restrict__ neg, const float* __restrict__ item_emb) {
    int lane = threadIdx.x & 31;
    int warp = (blockIdx.x * blockDim.x + threadIdx.x) >> 5;
    if (warp >= BATCH) return;
    const int FW = D * (NL + 1);  // 512
    size_t ur = (size_t)user[warp];
    size_t pr = (size_t)U_CNT + pos[warp];
    size_t nr = (size_t)U_CNT + neg[warp];
    const float4* u4 = (const float4*)(g_final + ur * FW);
    const float4* p4 = (const float4*)(g_final + pr * FW);
    const float4* n4 = (const float4*)(g_final + nr * FW);
    float ps = 0.f, ns = 0.f;
#pragma unroll
    for (int t = 0; t < 4; t++) {
        float4 u = u4[lane + 32 * t];
        float4 p = p4[lane + 32 * t];
        float4 n = n4[lane + 32 * t];
        ps += u.x * p.x + u.y * p.y + u.z * p.z + u.w * p.w;
        ns += u.x * n.x + u.y * n.y + u.z * n.z + u.w * n.w;
    }
    float4 a = ((const float4*)(item_emb + (size_t)pos[warp] * D))[lane];
    float4 b = ((const float4*)(item_emb + (size_t)neg[warp] * D))[lane];
    float rs = a.x * a.x + a.y * a.y + a.z * a.z + a.w * a.w
             + b.x * b.x + b.y * b.y + b.z * b.z + b.w * b.w;
#pragma unroll
    for (int off = 16; off; off >>= 1) {
        ps += __shfl_xor_sync(0xffffffffu, ps, off);
        ns += __shfl_xor_sync(0xffffffffu, ns, off);
        rs += __shfl_xor_sync(0xffffffffu, rs, off);
    }
    if (lane == 0) {
        float x  = ns - ps;
        float sp = fmaxf(x, 0.f) + log1pf(expf(-fabsf(x)));
        atomicAdd(&g_acc[0], sp);
        atomicAdd(&g_acc[1], rs);
    }
}

__global__ void finalize_kernel(float* __restrict__ out) {
    out[0] = g_acc[0] / (float)BATCH;
    out[1] = 1e-4f * 0.5f * g_acc[1] / (float)BATCH;
}

// ---------------------------------------------------------------------------
extern "C" void kernel_launch(void* const* d_in, const int* in_sizes, int n_in,
                              void* d_out, int out_size) {
    const int*   user = (const int*)d_in[0];
    const int*   pos  = (const int*)d_in[1];
    const int*   neg  = (const int*)d_in[2];
    const int*   erow = (const int*)d_in[3];
    const int*   ecol = (const int*)d_in[4];
    const float* evalp = (const float*)d_in[5];
    const float* ue   = (const float*)d_in[6];
    const float* ie   = (const float*)d_in[7];
    const float* Wg   = (const float*)d_in[8];
    const float* bg   = (const float*)d_in[9];
    const float* Wb   = (const float*)d_in[10];
    const float* bb   = (const float*)d_in[11];
    float* out = (float*)d_out;
    int nnz = in_sizes[3];
    if (nnz > MAXE) nnz = MAXE;

    cudaFuncSetAttribute(transform_mma_kernel,
                         cudaFuncAttributeMaxDynamicSharedMemorySize, SMEM_BYTES);

    {
        int total = N_CNT * (D / 4);
        init_kernel<<<(total + 255) / 256, 256>>>(ue, ie);
    }
    // Build row-sorted CSR once, reused by all 3 layers
    hist_kernel<<<(nnz + 255) / 256, 256>>>(erow, nnz);
    scan1_kernel<<<SCAN_BLOCKS, 256>>>();
    scan2_kernel<<<1, 128>>>();
    scan3_kernel<<<(N_CNT + 255) / 256, 256>>>(nnz);
    scatter_kernel<<<(nnz + 255) / 256, 256>>>(erow, ecol, evalp, nnz);

    for (int l = 0; l < NL; l++) {
        spmm_csr_kernel<<<(N_CNT * 32 + 255) / 256, 256>>>();
        transform_mma_kernel<<<(N_CNT + 63) / 64, 256, SMEM_BYTES>>>(
            Wg + (size_t)l * D * D, Wb + (size_t)l * D * D,
            bg + (size_t)l * D,     bb + (size_t)l * D,
            l + 1, (l < NL - 1) ? 1 : 0);
    }
    loss_kernel<<<(BATCH * 32 + 255) / 256, 256>>>(user, pos, neg, ie);
    finalize_kernel<<<1, 1>>>(out);
}

// round 16
// speedup vs baseline: 1.8094x; 1.1499x over previous
#include <cuda_runtime.h>
#include <cuda_bf16.h>
#include <cuda_fp16.h>
#include <cstdint>

#define U_CNT 50000
#define I_CNT 100000
#define N_CNT 150000
#define D 128
#define NL 3
#define BATCH 4096
#define MAXE 4800000
#define SCAN_ELEMS 2048
#define SCAN_BLOCKS ((N_CNT + SCAN_ELEMS - 1) / SCAN_ELEMS)   // 74

// transform tiling
#define A_STRIDE 260            // 64 x 260 staged A ([side|prod]), pad: 260%32=4
#define B_STRIDE 136            // 64 x 136 staged B chunk,        pad: 136%32=8
#define O_STRIDE 132            // 64 x 132 epilogue tile
#define SMF_B    (64 * A_STRIDE)                       // float offset of B region
#define SMEM_FLOATS (64 * A_STRIDE + 64 * B_STRIDE)    // 25344 floats
#define SMEM_BYTES  (SMEM_FLOATS * 4)                  // 101376 B

// Scratch (device globals: the allowed scratch mechanism)
__device__ float  g_ego [(size_t)N_CNT * D];            // fp32 ego (bi-term source)
__device__ __half g_egoh[(size_t)N_CNT * D];            // fp16 mirror (gather source)
__device__ float  g_side[(size_t)N_CNT * D];            // SpMM output
__device__ float  g_final[(size_t)N_CNT * D * (NL + 1)]; // [N, 512] concat
__device__ float  g_acc[2];                              // bpr sum, reg sum
// CSR-by-row edge structure, rebuilt each launch
__device__ int   g_cnt[N_CNT];
__device__ int   g_off[N_CNT + 1];
__device__ int   g_bsum[SCAN_BLOCKS];
__device__ int2  g_sedge[MAXE];       // (col, val-as-bits), row-sorted

// ---- tf32 helpers ---------------------------------------------------------
__device__ __forceinline__ float tf32r(float x) {
    uint32_t r;
    asm("cvt.rna.tf32.f32 %0, %1;" : "=r"(r) : "f"(x));
    return __uint_as_float(r);
}
__device__ __forceinline__ void mma_tf32(float* c, uint32_t a0, uint32_t a1,
                                         uint32_t a2, uint32_t a3,
                                         uint32_t b0, uint32_t b1) {
    asm("mma.sync.aligned.m16n8k8.row.col.f32.tf32.tf32.f32 "
        "{%0,%1,%2,%3},{%4,%5,%6,%7},{%8,%9},{%0,%1,%2,%3};"
        : "+f"(c[0]), "+f"(c[1]), "+f"(c[2]), "+f"(c[3])
        : "r"(a0), "r"(a1), "r"(a2), "r"(a3), "r"(b0), "r"(b1));
}

// ---- fp16 pack helper (clamped against overflow) --------------------------
__device__ __forceinline__ __half2 h2clamp(float a, float b) {
    a = fminf(fmaxf(a, -60000.f), 60000.f);
    b = fminf(fmaxf(b, -60000.f), 60000.f);
    return __floats2half2_rn(a, b);
}

// ---------------------------------------------------------------------------
// init: ego/egoh = concat(user_emb, item_emb); final[:, :128] = ego; cnt = 0
// ---------------------------------------------------------------------------
__global__ void init_kernel(const float* __restrict__ ue, const float* __restrict__ ie) {
    size_t i = (size_t)blockIdx.x * blockDim.x + threadIdx.x;  // float4 index
    if (i == 0) { g_acc[0] = 0.f; g_acc[1] = 0.f; }
    if (i >= (size_t)N_CNT * (D / 4)) return;
    size_t row = i >> 5;
    int    c4  = (int)(i & 31);
    if (c4 == 0) g_cnt[row] = 0;
    float4 v;
    if (row < U_CNT) v = ((const float4*)ue)[row * (D / 4) + c4];
    else             v = ((const float4*)ie)[(row - U_CNT) * (D / 4) + c4];
    ((float4*)g_ego)[i] = v;
    __half2 h0 = h2clamp(v.x, v.y);
    __half2 h1 = h2clamp(v.z, v.w);
    uint2 hb;
    hb.x = *(unsigned int*)&h0;
    hb.y = *(unsigned int*)&h1;
    ((uint2*)g_egoh)[i] = hb;
    ((float4*)(g_final + row * (size_t)(D * (NL + 1))))[c4] = v;
}

// ---------------------------------------------------------------------------
// CSR build: histogram -> 3-phase exclusive scan -> scatter
// ---------------------------------------------------------------------------
__global__ void hist_kernel(const int* __restrict__ erow, int nnz) {
    int e = blockIdx.x * blockDim.x + threadIdx.x;
    if (e < nnz) atomicAdd(&g_cnt[erow[e]], 1);
}

__global__ void __launch_bounds__(256) scan1_kernel() {
    __shared__ int s_warp[8];
    int b = blockIdx.x, t = threadIdx.x;
    int lane = t & 31, wid = t >> 5;
    int base = b * SCAN_ELEMS + t * 8;
    int v[8], tot = 0;
#pragma unroll
    for (int j = 0; j < 8; j++) {
        int idx = base + j;
        v[j] = (idx < N_CNT) ? g_cnt[idx] : 0;
        tot += v[j];
    }
    int inc = tot;
#pragma unroll
    for (int off = 1; off < 32; off <<= 1) {
        int y = __shfl_up_sync(0xffffffffu, inc, off);
        if (lane >= off) inc += y;
    }
    if (lane == 31) s_warp[wid] = inc;
    __syncthreads();
    if (t < 8) {
        int w = s_warp[t];
        int winc = w;
#pragma unroll
        for (int off = 1; off < 8; off <<= 1) {
            int y = __shfl_up_sync(0xffu, winc, off);
            if (t >= off) winc += y;
        }
        s_warp[t] = winc - w;
    }
    __syncthreads();
    int run = inc - tot + s_warp[wid];
    if (t == 255) g_bsum[b] = run + tot;
#pragma unroll
    for (int j = 0; j < 8; j++) {
        int idx = base + j;
        if (idx < N_CNT) g_off[idx] = run;
        run += v[j];
    }
}

__global__ void scan2_kernel() {
    __shared__ int s_warp[4];
    int t = threadIdx.x, lane = t & 31, wid = t >> 5;
    int x = (t < SCAN_BLOCKS) ? g_bsum[t] : 0;
    int inc = x;
#pragma unroll
    for (int off = 1; off < 32; off <<= 1) {
        int y = __shfl_up_sync(0xffffffffu, inc, off);
        if (lane >= off) inc += y;
    }
    if (lane == 31) s_warp[wid] = inc;
    __syncthreads();
    if (t < 4) {
        int w = s_warp[t];
        int winc = w;
#pragma unroll
        for (int off = 1; off < 4; off <<= 1) {
            int y = __shfl_up_sync(0xfu, winc, off);
            if (t >= off) winc += y;
        }
        s_warp[t] = winc - w;
    }
    __syncthreads();
    if (t < SCAN_BLOCKS) g_bsum[t] = inc - x + s_warp[wid];
}

__global__ void scan3_kernel(int nnz) {
    int i = blockIdx.x * blockDim.x + threadIdx.x;
    if (i == 0) g_off[N_CNT] = nnz;
    if (i >= N_CNT) return;
    int o = g_off[i] + g_bsum[i >> 11];  // SCAN_ELEMS = 2048
    g_off[i] = o;
    g_cnt[i] = o;
}

__global__ void scatter_kernel(const int* __restrict__ erow, const int* __restrict__ ecol,
                               const float* __restrict__ ev, int nnz) {
    int e = blockIdx.x * blockDim.x + threadIdx.x;
    if (e >= nnz) return;
    int r = erow[e];
    int pos = atomicAdd(&g_cnt[r], 1);
    g_sedge[pos] = make_int2(ecol[e], __float_as_int(ev[e]));
}

// ---------------------------------------------------------------------------
// spmm (CSR): one warp per row, fp16 gather (halved L2 bytes), fp32 accumulate
// lane owns 4 cols: loads uint2 = 4 halves per edge.
// ---------------------------------------------------------------------------
__global__ void __launch_bounds__(256) spmm_csr_kernel() {
    int lane = threadIdx.x & 31;
    int row  = (blockIdx.x * blockDim.x + threadIdx.x) >> 5;
    if (row >= N_CNT) return;
    int s = __ldg(&g_off[row]);
    int e = __ldg(&g_off[row + 1]);
    float4 acc = make_float4(0.f, 0.f, 0.f, 0.f);
    for (int base = s; base < e; base += 32) {
        int n = min(32, e - base);
        int2 ed = (lane < n) ? g_sedge[base + lane] : make_int2(0, 0);
        for (int j = 0; j < n; j++) {
            int   col = __shfl_sync(0xffffffffu, ed.x, j);
            float v   = __int_as_float(__shfl_sync(0xffffffffu, ed.y, j));
            uint2 h = __ldg(((const uint2*)(g_egoh + (size_t)col * D)) + lane);
            float2 lo = __half22float2(*(__half2*)&h.x);
            float2 hi = __half22float2(*(__half2*)&h.y);
            acc.x += v * lo.x; acc.y += v * lo.y;
            acc.z += v * hi.x; acc.w += v * hi.y;
        }
    }
    __stcs(((float4*)(g_side + (size_t)row * D)) + lane, acc);
}

// ---------------------------------------------------------------------------
// transform (tf32 tensor cores):
//   out = lrelu([side | side*ego] @ [Wg ; Wb] + bg + bb)
//   ego/egoh = out (if not last layer); final[:, (l+1)*128:] = out / ||out||
// ---------------------------------------------------------------------------
__global__ void __launch_bounds__(256) transform_mma_kernel(
    const float* __restrict__ Wg, const float* __restrict__ Wb,
    const float* __restrict__ bg, const float* __restrict__ bb,
    int lplus1, int write_ego) {
    extern __shared__ float sm[];
    float* sA = sm;            // [64][A_STRIDE]  (cols 0..127 side, 128..255 prod)
    float* sB = sm + SMF_B;    // [64][B_STRIDE]  per-chunk W tile
    float* sO = sm + SMF_B;    // [64][O_STRIDE]  epilogue reuse of B region

    const int tid  = threadIdx.x;
    const int row0 = blockIdx.x * 64;
    const int lane = tid & 31;
    const int w    = tid >> 5;
    const int gid  = lane >> 2;    // 0..7
    const int tig  = lane & 3;     // 0..3
    const int rs   = w >> 1;       // row strip 0..3
    const int ch   = w & 1;        // col half 0..1

    // ---- stage A: [side | side*ego] as tf32 -------------------------------
    for (int idx = tid; idx < 64 * 32; idx += 256) {
        int r  = idx >> 5;
        int c4 = idx & 31;
        int gr = row0 + r;
        float4 sd = make_float4(0.f, 0.f, 0.f, 0.f);
        float4 eg = sd;
        if (gr < N_CNT) {
            sd = __ldcs(((const float4*)(g_side + (size_t)gr * D)) + c4);
            eg = ((const float4*)(g_ego + (size_t)gr * D))[c4];
        }
        float* pa = sA + r * A_STRIDE + c4 * 4;
        pa[0] = tf32r(sd.x); pa[1] = tf32r(sd.y);
        pa[2] = tf32r(sd.z); pa[3] = tf32r(sd.w);
        float* pp = pa + 128;
        pp[0] = tf32r(sd.x * eg.x); pp[1] = tf32r(sd.y * eg.y);
        pp[2] = tf32r(sd.z * eg.z); pp[3] = tf32r(sd.w * eg.w);
    }

    float c[8][4];
#pragma unroll
    for (int nt = 0; nt < 8; nt++)
#pragma unroll
        for (int i = 0; i < 4; i++) c[nt][i] = 0.f;

    // ---- main loop over 4 K-chunks of 64 ----------------------------------
    for (int kc = 0; kc < 4; kc++) {
        __syncthreads();  // also covers A staging on first iter; sB reuse after
        const float* Wsrc = (kc < 2) ? Wg : Wb;
        const int kr0 = (kc & 1) * 64;
        for (int idx = tid; idx < 64 * 32; idx += 256) {
            int k  = idx >> 5;
            int c4 = idx & 31;
            float4 wv = __ldg((const float4*)(Wsrc + (size_t)(kr0 + k) * D + c4 * 4));
            float* pb = sB + k * B_STRIDE + c4 * 4;
            pb[0] = tf32r(wv.x); pb[1] = tf32r(wv.y);
            pb[2] = tf32r(wv.z); pb[3] = tf32r(wv.w);
        }
        __syncthreads();

        const float* Ab = sA + (rs * 16) * A_STRIDE + kc * 64;
#pragma unroll
        for (int ks = 0; ks < 8; ks++) {
            const int kl = ks * 8;
            uint32_t a0 = __float_as_uint(Ab[gid * A_STRIDE + kl + tig]);
            uint32_t a1 = __float_as_uint(Ab[(gid + 8) * A_STRIDE + kl + tig]);
            uint32_t a2 = __float_as_uint(Ab[gid * A_STRIDE + kl + tig + 4]);
            uint32_t a3 = __float_as_uint(Ab[(gid + 8) * A_STRIDE + kl + tig + 4]);
            const float* Bb = sB + (kl + tig) * B_STRIDE + ch * 64 + gid;
#pragma unroll
            for (int nt = 0; nt < 8; nt++) {
                uint32_t b0 = __float_as_uint(Bb[nt * 8]);
                uint32_t b1 = __float_as_uint(Bb[4 * B_STRIDE + nt * 8]);
                mma_tf32(c[nt], a0, a1, a2, a3, b0, b1);
            }
        }
    }
    __syncthreads();  // done reading sB; safe to overwrite as sO

    // ---- bias + lrelu, frags -> sO ----------------------------------------
    const int ra = rs * 16 + gid;
    const int rb = ra + 8;
#pragma unroll
    for (int nt = 0; nt < 8; nt++) {
        int col = ch * 64 + nt * 8 + 2 * tig;
        float b0v = __ldg(bg + col) + __ldg(bb + col);
        float b1v = __ldg(bg + col + 1) + __ldg(bb + col + 1);
        float x0 = c[nt][0] + b0v; x0 = (x0 >= 0.f) ? x0 : 0.2f * x0;
        float x1 = c[nt][1] + b1v; x1 = (x1 >= 0.f) ? x1 : 0.2f * x1;
        float x2 = c[nt][2] + b0v; x2 = (x2 >= 0.f) ? x2 : 0.2f * x2;
        float x3 = c[nt][3] + b1v; x3 = (x3 >= 0.f) ? x3 : 0.2f * x3;
        *(float2*)(sO + ra * O_STRIDE + col) = make_float2(x0, x1);
        *(float2*)(sO + rb * O_STRIDE + col) = make_float2(x2, x3);
    }
    __syncthreads();

    // ---- row norm + global writes (4 threads per row, 32 cols each) -------
    {
        int r     = tid >> 2;
        int cpart = (tid & 3) * 32;
        int gr    = row0 + r;
        float4 vv[8];
        float ss = 0.f;
#pragma unroll
        for (int i = 0; i < 8; i++) {
            vv[i] = *(const float4*)(sO + r * O_STRIDE + cpart + i * 4);
            ss += vv[i].x * vv[i].x + vv[i].y * vv[i].y
                + vv[i].z * vv[i].z + vv[i].w * vv[i].w;
        }
        ss += __shfl_xor_sync(0xffffffffu, ss, 1);
        ss += __shfl_xor_sync(0xffffffffu, ss, 2);
        float inv = 1.0f / fmaxf(sqrtf(ss), 1e-12f);
        if (gr < N_CNT) {
            float4* eo = (float4*)(g_ego + (size_t)gr * D + cpart);
            float*  fo = g_final + (size_t)gr * (D * (NL + 1)) + (size_t)lplus1 * D + cpart;
#pragma unroll
            for (int i = 0; i < 8; i++) {
                if (write_ego) eo[i] = vv[i];
                __stcs((float4*)fo + i,
                       make_float4(vv[i].x * inv, vv[i].y * inv,
                                   vv[i].z * inv, vv[i].w * inv));
            }
            if (write_ego) {
                uint2* ho = (uint2*)(g_egoh + (size_t)gr * D + cpart);
#pragma unroll
                for (int i = 0; i < 8; i++) {
                    __half2 h0 = h2clamp(vv[i].x, vv[i].y);
                    __half2 h1 = h2clamp(vv[i].z, vv[i].w);
                    uint2 hb;
                    hb.x = *(unsigned int*)&h0;
                    hb.y = *(unsigned int*)&h1;
                    ho[i] = hb;
                }
            }
        }
    }
}

// ---------------------------------------------------------------------------
// loss: one warp per batch sample
// ---------------------------------------------------------------------------
__global__ void loss_kernel(const int* __restrict__ user, const int* __restrict__ pos,
                            const int* __restrict__ neg, const float* __restrict__ item_emb) {
    int lane = threadIdx.x & 31;
    int warp = (blockIdx.x * blockDim.x + threadIdx.x) >> 5;
    if (warp >= BATCH) return;
    const int FW = D * (NL + 1);  // 512
    size_t ur = (size_t)user[warp];
    size_t pr = (size_t)U_CNT + pos[warp];
    size_t nr = (size_t)U_CNT + neg[warp];
    const float4* u4 = (const float4*)(g_final + ur * FW);
    const float4* p4 = (const float4*)(g_final + pr * FW);
    const float4* n4 = (const float4*)(g_final + nr * FW);
    float ps = 0.f, ns = 0.f;
#pragma unroll
    for (int t = 0; t < 4; t++) {
        float4 u = u4[lane + 32 * t];
        float4 p = p4[lane + 32 * t];
        float4 n = n4[lane + 32 * t];
        ps += u.x * p.x + u.y * p.y + u.z * p.z + u.w * p.w;
        ns += u.x * n.x + u.y * n.y + u.z * n.z + u.w * n.w;
    }
    float4 a = ((const float4*)(item_emb + (size_t)pos[warp] * D))[lane];
    float4 b = ((const float4*)(item_emb + (size_t)neg[warp] * D))[lane];
    float rs = a.x * a.x + a.y * a.y + a.z * a.z + a.w * a.w
             + b.x * b.x + b.y * b.y + b.z * b.z + b.w * b.w;
#pragma unroll
    for (int off = 16; off; off >>= 1) {
        ps += __shfl_xor_sync(0xffffffffu, ps, off);
        ns += __shfl_xor_sync(0xffffffffu, ns, off);
        rs += __shfl_xor_sync(0xffffffffu, rs, off);
    }
    if (lane == 0) {
        float x  = ns - ps;
        float sp = fmaxf(x, 0.f) + log1pf(expf(-fabsf(x)));
        atomicAdd(&g_acc[0], sp);
        atomicAdd(&g_acc[1], rs);
    }
}

__global__ void finalize_kernel(float* __restrict__ out) {
    out[0] = g_acc[0] / (float)BATCH;
    out[1] = 1e-4f * 0.5f * g_acc[1] / (float)BATCH;
}

// ---------------------------------------------------------------------------
extern "C" void kernel_launch(void* const* d_in, const int* in_sizes, int n_in,
                              void* d_out, int out_size) {
    const int*   user = (const int*)d_in[0];
    const int*   pos  = (const int*)d_in[1];
    const int*   neg  = (const int*)d_in[2];
    const int*   erow = (const int*)d_in[3];
    const int*   ecol = (const int*)d_in[4];
    const float* evalp = (const float*)d_in[5];
    const float* ue   = (const float*)d_in[6];
    const float* ie   = (const float*)d_in[7];
    const float* Wg   = (const float*)d_in[8];
    const float* bg   = (const float*)d_in[9];
    const float* Wb   = (const float*)d_in[10];
    const float* bb   = (const float*)d_in[11];
    float* out = (float*)d_out;
    int nnz = in_sizes[3];
    if (nnz > MAXE) nnz = MAXE;

    cudaFuncSetAttribute(transform_mma_kernel,
                         cudaFuncAttributeMaxDynamicSharedMemorySize, SMEM_BYTES);

    {
        int total = N_CNT * (D / 4);
        init_kernel<<<(total + 255) / 256, 256>>>(ue, ie);
    }
    // Build row-sorted CSR once, reused by all 3 layers
    hist_kernel<<<(nnz + 255) / 256, 256>>>(erow, nnz);
    scan1_kernel<<<SCAN_BLOCKS, 256>>>();
    scan2_kernel<<<1, 128>>>();
    scan3_kernel<<<(N_CNT + 255) / 256, 256>>>(nnz);
    scatter_kernel<<<(nnz + 255) / 256, 256>>>(erow, ecol, evalp, nnz);

    for (int l = 0; l < NL; l++) {
        spmm_csr_kernel<<<(N_CNT * 32 + 255) / 256, 256>>>();
        transform_mma_kernel<<<(N_CNT + 63) / 64, 256, SMEM_BYTES>>>(
            Wg + (size_t)l * D * D, Wb + (size_t)l * D * D,
            bg + (size_t)l * D,     bb + (size_t)l * D,
            l + 1, (l < NL - 1) ? 1 : 0);
    }
    loss_kernel<<<(BATCH * 32 + 255) / 256, 256>>>(user, pos, neg, ie);
    finalize_kernel<<<1, 1>>>(out);
}

// round 17
// speedup vs baseline: 2.0708x; 1.1445x over previous
#include <cuda_runtime.h>
#include <cuda_bf16.h>
#include <cuda_fp16.h>
#include <cstdint>

#define U_CNT 50000
#define I_CNT 100000
#define N_CNT 150000
#define D 128
#define NL 3
#define BATCH 4096
#define MAXE 4800000
#define SCAN_ELEMS 2048
#define SCAN_BLOCKS ((N_CNT + SCAN_ELEMS - 1) / SCAN_ELEMS)   // 74

// transform tiling
#define A_STRIDE 260            // 64 x 260 staged A ([side|prod]), pad: 260%32=4
#define B_STRIDE 136            // 64 x 136 staged B chunk,        pad: 136%32=8
#define O_STRIDE 132            // 64 x 132 epilogue tile
#define SMF_B    (64 * A_STRIDE)                       // float offset of B region
#define SMEM_FLOATS (64 * A_STRIDE + 64 * B_STRIDE)    // 25344 floats
#define SMEM_BYTES  (SMEM_FLOATS * 4)                  // 101376 B

// Scratch (device globals: the allowed scratch mechanism)
__device__ float  g_ego  [(size_t)N_CNT * D];            // fp32 ego (bi-term source)
__device__ __half g_egoh [(size_t)N_CNT * D];            // fp16 mirror (gather source)
__device__ __half g_sideh[(size_t)N_CNT * D];            // fp16 SpMM output
__device__ float  g_final[(size_t)N_CNT * D * (NL + 1)]; // [N, 512] concat (flagged rows only)
__device__ float  g_acc[2];                              // bpr sum, reg sum
__device__ unsigned char g_flag[N_CNT];                  // rows needed by loss
// CSR-by-row edge structure, rebuilt each launch
__device__ int   g_cnt[N_CNT];
__device__ int   g_off[N_CNT + 1];
__device__ int   g_bsum[SCAN_BLOCKS];
__device__ int2  g_sedge[MAXE];       // (col, val-as-bits), row-sorted

// ---- tf32 helpers ---------------------------------------------------------
__device__ __forceinline__ float tf32r(float x) {
    uint32_t r;
    asm("cvt.rna.tf32.f32 %0, %1;" : "=r"(r) : "f"(x));
    return __uint_as_float(r);
}
__device__ __forceinline__ void mma_tf32(float* c, uint32_t a0, uint32_t a1,
                                         uint32_t a2, uint32_t a3,
                                         uint32_t b0, uint32_t b1) {
    asm("mma.sync.aligned.m16n8k8.row.col.f32.tf32.tf32.f32 "
        "{%0,%1,%2,%3},{%4,%5,%6,%7},{%8,%9},{%0,%1,%2,%3};"
        : "+f"(c[0]), "+f"(c[1]), "+f"(c[2]), "+f"(c[3])
        : "r"(a0), "r"(a1), "r"(a2), "r"(a3), "r"(b0), "r"(b1));
}

// ---- fp16 pack helper (clamped against overflow) --------------------------
__device__ __forceinline__ __half2 h2clamp(float a, float b) {
    a = fminf(fmaxf(a, -60000.f), 60000.f);
    b = fminf(fmaxf(b, -60000.f), 60000.f);
    return __floats2half2_rn(a, b);
}

// ---------------------------------------------------------------------------
// prep: zero flags + counters; then flag sampled rows
// ---------------------------------------------------------------------------
__global__ void prep_kernel() {
    int i = blockIdx.x * blockDim.x + threadIdx.x;
    if (i == 0) { g_acc[0] = 0.f; g_acc[1] = 0.f; }
    if (i < N_CNT) { g_cnt[i] = 0; g_flag[i] = 0; }
}

__global__ void flag_kernel(const int* __restrict__ user, const int* __restrict__ pos,
                            const int* __restrict__ neg) {
    int i = blockIdx.x * blockDim.x + threadIdx.x;
    if (i >= BATCH) return;
    g_flag[user[i]] = 1;
    g_flag[U_CNT + pos[i]] = 1;
    g_flag[U_CNT + neg[i]] = 1;
}

// ---------------------------------------------------------------------------
// init: ego/egoh = concat(user_emb, item_emb); final[:, :128] = ego (flagged)
// ---------------------------------------------------------------------------
__global__ void init_kernel(const float* __restrict__ ue, const float* __restrict__ ie) {
    size_t i = (size_t)blockIdx.x * blockDim.x + threadIdx.x;  // float4 index
    if (i >= (size_t)N_CNT * (D / 4)) return;
    size_t row = i >> 5;
    int    c4  = (int)(i & 31);
    float4 v;
    if (row < U_CNT) v = ((const float4*)ue)[row * (D / 4) + c4];
    else             v = ((const float4*)ie)[(row - U_CNT) * (D / 4) + c4];
    ((float4*)g_ego)[i] = v;
    __half2 h0 = h2clamp(v.x, v.y);
    __half2 h1 = h2clamp(v.z, v.w);
    uint2 hb;
    hb.x = *(unsigned int*)&h0;
    hb.y = *(unsigned int*)&h1;
    ((uint2*)g_egoh)[i] = hb;
    if (g_flag[row])
        ((float4*)(g_final + row * (size_t)(D * (NL + 1))))[c4] = v;
}

// ---------------------------------------------------------------------------
// CSR build: histogram -> 3-phase exclusive scan -> scatter
// ---------------------------------------------------------------------------
__global__ void hist_kernel(const int* __restrict__ erow, int nnz) {
    int e = blockIdx.x * blockDim.x + threadIdx.x;
    if (e < nnz) atomicAdd(&g_cnt[erow[e]], 1);
}

__global__ void __launch_bounds__(256) scan1_kernel() {
    __shared__ int s_warp[8];
    int b = blockIdx.x, t = threadIdx.x;
    int lane = t & 31, wid = t >> 5;
    int base = b * SCAN_ELEMS + t * 8;
    int v[8], tot = 0;
#pragma unroll
    for (int j = 0; j < 8; j++) {
        int idx = base + j;
        v[j] = (idx < N_CNT) ? g_cnt[idx] : 0;
        tot += v[j];
    }
    int inc = tot;
#pragma unroll
    for (int off = 1; off < 32; off <<= 1) {
        int y = __shfl_up_sync(0xffffffffu, inc, off);
        if (lane >= off) inc += y;
    }
    if (lane == 31) s_warp[wid] = inc;
    __syncthreads();
    if (t < 8) {
        int w = s_warp[t];
        int winc = w;
#pragma unroll
        for (int off = 1; off < 8; off <<= 1) {
            int y = __shfl_up_sync(0xffu, winc, off);
            if (t >= off) winc += y;
        }
        s_warp[t] = winc - w;
    }
    __syncthreads();
    int run = inc - tot + s_warp[wid];
    if (t == 255) g_bsum[b] = run + tot;
#pragma unroll
    for (int j = 0; j < 8; j++) {
        int idx = base + j;
        if (idx < N_CNT) g_off[idx] = run;
        run += v[j];
    }
}

__global__ void scan2_kernel() {
    __shared__ int s_warp[4];
    int t = threadIdx.x, lane = t & 31, wid = t >> 5;
    int x = (t < SCAN_BLOCKS) ? g_bsum[t] : 0;
    int inc = x;
#pragma unroll
    for (int off = 1; off < 32; off <<= 1) {
        int y = __shfl_up_sync(0xffffffffu, inc, off);
        if (lane >= off) inc += y;
    }
    if (lane == 31) s_warp[wid] = inc;
    __syncthreads();
    if (t < 4) {
        int w = s_warp[t];
        int winc = w;
#pragma unroll
        for (int off = 1; off < 4; off <<= 1) {
            int y = __shfl_up_sync(0xfu, winc, off);
            if (t >= off) winc += y;
        }
        s_warp[t] = winc - w;
    }
    __syncthreads();
    if (t < SCAN_BLOCKS) g_bsum[t] = inc - x + s_warp[wid];
}

__global__ void scan3_kernel(int nnz) {
    int i = blockIdx.x * blockDim.x + threadIdx.x;
    if (i == 0) g_off[N_CNT] = nnz;
    if (i >= N_CNT) return;
    int o = g_off[i] + g_bsum[i >> 11];  // SCAN_ELEMS = 2048
    g_off[i] = o;
    g_cnt[i] = o;
}

__global__ void scatter_kernel(const int* __restrict__ erow, const int* __restrict__ ecol,
                               const float* __restrict__ ev, int nnz) {
    int e = blockIdx.x * blockDim.x + threadIdx.x;
    if (e >= nnz) return;
    int r = erow[e];
    int pos = atomicAdd(&g_cnt[r], 1);
    g_sedge[pos] = make_int2(ecol[e], __float_as_int(ev[e]));
}

// ---------------------------------------------------------------------------
// spmm (CSR): one warp per row, fp16 gather, fp32 accumulate, fp16 store.
// Edge (col,val) fetched via uniform-address broadcast load (no shuffles).
// ---------------------------------------------------------------------------
__global__ void __launch_bounds__(256) spmm_csr_kernel() {
    int lane = threadIdx.x & 31;
    int row  = (blockIdx.x * blockDim.x + threadIdx.x) >> 5;
    if (row >= N_CNT) return;
    int s = __ldg(&g_off[row]);
    int e = __ldg(&g_off[row + 1]);
    float4 acc = make_float4(0.f, 0.f, 0.f, 0.f);
    for (int j = s; j < e; j++) {
        int2  ed = __ldg(&g_sedge[j]);        // uniform across warp -> broadcast
        float v  = __int_as_float(ed.y);
        uint2 h  = __ldg(((const uint2*)(g_egoh + (size_t)ed.x * D)) + lane);
        float2 lo = __half22float2(*(__half2*)&h.x);
        float2 hi = __half22float2(*(__half2*)&h.y);
        acc.x += v * lo.x; acc.y += v * lo.y;
        acc.z += v * hi.x; acc.w += v * hi.y;
    }
    __half2 h0 = h2clamp(acc.x, acc.y);
    __half2 h1 = h2clamp(acc.z, acc.w);
    uint2 hb;
    hb.x = *(unsigned int*)&h0;
    hb.y = *(unsigned int*)&h1;
    __stcs(((uint2*)(g_sideh + (size_t)row * D)) + lane, hb);
}

// ---------------------------------------------------------------------------
// transform (tf32 tensor cores):
//   out = lrelu([side | side*ego] @ [Wg ; Wb] + bg + bb)
//   ego/egoh = out (if not last layer); final[:, (l+1)*128:] = out/||out|| (flagged)
// ---------------------------------------------------------------------------
__global__ void __launch_bounds__(256) transform_mma_kernel(
    const float* __restrict__ Wg, const float* __restrict__ Wb,
    const float* __restrict__ bg, const float* __restrict__ bb,
    int lplus1, int write_ego) {
    extern __shared__ float sm[];
    float* sA = sm;            // [64][A_STRIDE]  (cols 0..127 side, 128..255 prod)
    float* sB = sm + SMF_B;    // [64][B_STRIDE]  per-chunk W tile
    float* sO = sm + SMF_B;    // [64][O_STRIDE]  epilogue reuse of B region

    const int tid  = threadIdx.x;
    const int row0 = blockIdx.x * 64;
    const int lane = tid & 31;
    const int w    = tid >> 5;
    const int gid  = lane >> 2;    // 0..7
    const int tig  = lane & 3;     // 0..3
    const int rs   = w >> 1;       // row strip 0..3
    const int ch   = w & 1;        // col half 0..1

    // ---- stage A: [side | side*ego] as tf32 (side from fp16) --------------
    for (int idx = tid; idx < 64 * 32; idx += 256) {
        int r  = idx >> 5;
        int c4 = idx & 31;
        int gr = row0 + r;
        float4 sd = make_float4(0.f, 0.f, 0.f, 0.f);
        float4 eg = sd;
        if (gr < N_CNT) {
            uint2 hh = __ldcs(((const uint2*)(g_sideh + (size_t)gr * D)) + c4);
            float2 lo = __half22float2(*(__half2*)&hh.x);
            float2 hi = __half22float2(*(__half2*)&hh.y);
            sd = make_float4(lo.x, lo.y, hi.x, hi.y);
            eg = ((const float4*)(g_ego + (size_t)gr * D))[c4];
        }
        float* pa = sA + r * A_STRIDE + c4 * 4;
        pa[0] = sd.x; pa[1] = sd.y;       // fp16 values are already tf32-exact
        pa[2] = sd.z; pa[3] = sd.w;
        float* pp = pa + 128;
        pp[0] = tf32r(sd.x * eg.x); pp[1] = tf32r(sd.y * eg.y);
        pp[2] = tf32r(sd.z * eg.z); pp[3] = tf32r(sd.w * eg.w);
    }

    float c[8][4];
#pragma unroll
    for (int nt = 0; nt < 8; nt++)
#pragma unroll
        for (int i = 0; i < 4; i++) c[nt][i] = 0.f;

    // ---- main loop over 4 K-chunks of 64 ----------------------------------
    for (int kc = 0; kc < 4; kc++) {
        __syncthreads();  // also covers A staging on first iter; sB reuse after
        const float* Wsrc = (kc < 2) ? Wg : Wb;
        const int kr0 = (kc & 1) * 64;
        for (int idx = tid; idx < 64 * 32; idx += 256) {
            int k  = idx >> 5;
            int c4 = idx & 31;
            float4 wv = __ldg((const float4*)(Wsrc + (size_t)(kr0 + k) * D + c4 * 4));
            float* pb = sB + k * B_STRIDE + c4 * 4;
            pb[0] = tf32r(wv.x); pb[1] = tf32r(wv.y);
            pb[2] = tf32r(wv.z); pb[3] = tf32r(wv.w);
        }
        __syncthreads();

        const float* Ab = sA + (rs * 16) * A_STRIDE + kc * 64;
#pragma unroll
        for (int ks = 0; ks < 8; ks++) {
            const int kl = ks * 8;
            uint32_t a0 = __float_as_uint(Ab[gid * A_STRIDE + kl + tig]);
            uint32_t a1 = __float_as_uint(Ab[(gid + 8) * A_STRIDE + kl + tig]);
            uint32_t a2 = __float_as_uint(Ab[gid * A_STRIDE + kl + tig + 4]);
            uint32_t a3 = __float_as_uint(Ab[(gid + 8) * A_STRIDE + kl + tig + 4]);
            const float* Bb = sB + (kl + tig) * B_STRIDE + ch * 64 + gid;
#pragma unroll
            for (int nt = 0; nt < 8; nt++) {
                uint32_t b0 = __float_as_uint(Bb[nt * 8]);
                uint32_t b1 = __float_as_uint(Bb[4 * B_STRIDE + nt * 8]);
                mma_tf32(c[nt], a0, a1, a2, a3, b0, b1);
            }
        }
    }
    __syncthreads();  // done reading sB; safe to overwrite as sO

    // ---- bias + lrelu, frags -> sO ----------------------------------------
    const int ra = rs * 16 + gid;
    const int rb = ra + 8;
#pragma unroll
    for (int nt = 0; nt < 8; nt++) {
        int col = ch * 64 + nt * 8 + 2 * tig;
        float b0v = __ldg(bg + col) + __ldg(bb + col);
        float b1v = __ldg(bg + col + 1) + __ldg(bb + col + 1);
        float x0 = c[nt][0] + b0v; x0 = (x0 >= 0.f) ? x0 : 0.2f * x0;
        float x1 = c[nt][1] + b1v; x1 = (x1 >= 0.f) ? x1 : 0.2f * x1;
        float x2 = c[nt][2] + b0v; x2 = (x2 >= 0.f) ? x2 : 0.2f * x2;
        float x3 = c[nt][3] + b1v; x3 = (x3 >= 0.f) ? x3 : 0.2f * x3;
        *(float2*)(sO + ra * O_STRIDE + col) = make_float2(x0, x1);
        *(float2*)(sO + rb * O_STRIDE + col) = make_float2(x2, x3);
    }
    __syncthreads();

    // ---- row norm + global writes (4 threads per row, 32 cols each) -------
    {
        int r     = tid >> 2;
        int cpart = (tid & 3) * 32;
        int gr    = row0 + r;
        float4 vv[8];
        float ss = 0.f;
#pragma unroll
        for (int i = 0; i < 8; i++) {
            vv[i] = *(const float4*)(sO + r * O_STRIDE + cpart + i * 4);
            ss += vv[i].x * vv[i].x + vv[i].y * vv[i].y
                + vv[i].z * vv[i].z + vv[i].w * vv[i].w;
        }
        ss += __shfl_xor_sync(0xffffffffu, ss, 1);
        ss += __shfl_xor_sync(0xffffffffu, ss, 2);
        float inv = 1.0f / fmaxf(sqrtf(ss), 1e-12f);
        if (gr < N_CNT) {
            if (write_ego) {
                float4* eo = (float4*)(g_ego + (size_t)gr * D + cpart);
                uint2*  ho = (uint2*)(g_egoh + (size_t)gr * D + cpart);
#pragma unroll
                for (int i = 0; i < 8; i++) {
                    eo[i] = vv[i];
                    __half2 h0 = h2clamp(vv[i].x, vv[i].y);
                    __half2 h1 = h2clamp(vv[i].z, vv[i].w);
                    uint2 hb;
                    hb.x = *(unsigned int*)&h0;
                    hb.y = *(unsigned int*)&h1;
                    ho[i] = hb;
                }
            }
            if (g_flag[gr]) {
                float* fo = g_final + (size_t)gr * (D * (NL + 1)) + (size_t)lplus1 * D + cpart;
#pragma unroll
                for (int i = 0; i < 8; i++)
                    __stcs((float4*)fo + i,
                           make_float4(vv[i].x * inv, vv[i].y * inv,
                                       vv[i].z * inv, vv[i].w * inv));
            }
        }
    }
}

// ---------------------------------------------------------------------------
// loss: one warp per batch sample
// ---------------------------------------------------------------------------
__global__ void loss_kernel(const int* __restrict__ user, const int* __restrict__ pos,
                            const int* __restrict__ neg, const float* __restrict__ item_emb) {
    int lane = threadIdx.x & 31;
    int warp = (blockIdx.x * blockDim.x + threadIdx.x) >> 5;
    if (warp >= BATCH) return;
    const int FW = D * (NL + 1);  // 512
    size_t ur = (size_t)user[warp];
    size_t pr = (size_t)U_CNT + pos[warp];
    size_t nr = (size_t)U_CNT + neg[warp];
    const float4* u4 = (const float4*)(g_final + ur * FW);
    const float4* p4 = (const float4*)(g_final + pr * FW);
    const float4* n4 = (const float4*)(g_final + nr * FW);
    float ps = 0.f, ns = 0.f;
#pragma unroll
    for (int t = 0; t < 4; t++) {
        float4 u = u4[lane + 32 * t];
        float4 p = p4[lane + 32 * t];
        float4 n = n4[lane + 32 * t];
        ps += u.x * p.x + u.y * p.y + u.z * p.z + u.w * p.w;
        ns += u.x * n.x + u.y * n.y + u.z * n.z + u.w * n.w;
    }
    float4 a = ((const float4*)(item_emb + (size_t)pos[warp] * D))[lane];
    float4 b = ((const float4*)(item_emb + (size_t)neg[warp] * D))[lane];
    float rs = a.x * a.x + a.y * a.y + a.z * a.z + a.w * a.w
             + b.x * b.x + b.y * b.y + b.z * b.z + b.w * b.w;
#pragma unroll
    for (int off = 16; off; off >>= 1) {
        ps += __shfl_xor_sync(0xffffffffu, ps, off);
        ns += __shfl_xor_sync(0xffffffffu, ns, off);
        rs += __shfl_xor_sync(0xffffffffu, rs, off);
    }
    if (lane == 0) {
        float x  = ns - ps;
        float sp = fmaxf(x, 0.f) + log1pf(expf(-fabsf(x)));
        atomicAdd(&g_acc[0], sp);
        atomicAdd(&g_acc[1], rs);
    }
}

__global__ void finalize_kernel(float* __restrict__ out) {
    out[0] = g_acc[0] / (float)BATCH;
    out[1] = 1e-4f * 0.5f * g_acc[1] / (float)BATCH;
}

// ---------------------------------------------------------------------------
extern "C" void kernel_launch(void* const* d_in, const int* in_sizes, int n_in,
                              void* d_out, int out_size) {
    const int*   user = (const int*)d_in[0];
    const int*   pos  = (const int*)d_in[1];
    const int*   neg  = (const int*)d_in[2];
    const int*   erow = (const int*)d_in[3];
    const int*   ecol = (const int*)d_in[4];
    const float* evalp = (const float*)d_in[5];
    const float* ue   = (const float*)d_in[6];
    const float* ie   = (const float*)d_in[7];
    const float* Wg   = (const float*)d_in[8];
    const float* bg   = (const float*)d_in[9];
    const float* Wb   = (const float*)d_in[10];
    const float* bb   = (const float*)d_in[11];
    float* out = (float*)d_out;
    int nnz = in_sizes[3];
    if (nnz > MAXE) nnz = MAXE;

    cudaFuncSetAttribute(transform_mma_kernel,
                         cudaFuncAttributeMaxDynamicSharedMemorySize, SMEM_BYTES);

    prep_kernel<<<(N_CNT + 255) / 256, 256>>>();
    flag_kernel<<<(BATCH + 255) / 256, 256>>>(user, pos, neg);
    {
        int total = N_CNT * (D / 4);
        init_kernel<<<(total + 255) / 256, 256>>>(ue, ie);
    }
    // Build row-sorted CSR once, reused by all 3 layers
    hist_kernel<<<(nnz + 255) / 256, 256>>>(erow, nnz);
    scan1_kernel<<<SCAN_BLOCKS, 256>>>();
    scan2_kernel<<<1, 128>>>();
    scan3_kernel<<<(N_CNT + 255) / 256, 256>>>(nnz);
    scatter_kernel<<<(nnz + 255) / 256, 256>>>(erow, ecol, evalp, nnz);

    for (int l = 0; l < NL; l++) {
        spmm_csr_kernel<<<(N_CNT * 32 + 255) / 256, 256>>>();
        transform_mma_kernel<<<(N_CNT + 63) / 64, 256, SMEM_BYTES>>>(
            Wg + (size_t)l * D * D, Wb + (size_t)l * D * D,
            bg + (size_t)l * D,     bb + (size_t)l * D,
            l + 1, (l < NL - 1) ? 1 : 0);
    }
    loss_kernel<<<(BATCH * 32 + 255) / 256, 256>>>(user, pos, neg, ie);
    finalize_kernel<<<1, 1>>>(out);
}